// round 13
// baseline (speedup 1.0000x reference)
#include <cuda_runtime.h>
#include <cstdint>

// Problem constants
#define T_ 1024
#define K_ 2
#define E_ 8
#define H_ 2048
#define I_ 1024

#define BM 128
#define KC 64            // K chunk in elements (= 32 fp16x2 words, 128B/row)
#define HKP 36           // smem row stride in fp16x2 words (32 used + 4 pad)
#define THREADS 256
#define MAX_TILES 24
#define CONV_X 8         // extra grid.x slots in gemm1 for dn conversion
#define STAGES 3
#define SBW (BM * HKP)                       // words per tile buffer (4608)
#define SMEM_BYTES (2 * STAGES * SBW * 4)    // As + Bs = 110592 bytes

// Scratch (device globals — allocation is forbidden)
__device__ int      g_pair_src[T_ * K_];
__device__ int      g_tile_e[MAX_TILES];
__device__ int      g_tile_start[MAX_TILES];
__device__ int      g_tile_cnt[MAX_TILES];
__device__ int      g_num_tiles;
__device__ uint32_t g_hs_h[(size_t)T_ * H_ / 2];             // fp16x2
__device__ uint32_t g_wgu_h[(size_t)E_ * 2 * I_ * H_ / 2];   // fp16x2
__device__ uint32_t g_dn_h[(size_t)E_ * H_ * I_ / 2];        // fp16x2
__device__ uint32_t g_inter_h[(size_t)T_ * K_ * I_ / 2];     // fp16x2

// ---------------------------------------------------------------- helpers
__device__ __forceinline__ uint32_t pack_h2(float lo, float hi) {
    uint32_t r; asm("cvt.rn.f16x2.f32 %0, %1, %2;" : "=r"(r) : "f"(hi), "f"(lo));
    return r;
}

__device__ __forceinline__ void mma_f16(float* c, const uint32_t* a, const uint32_t* b) {
    asm volatile(
        "mma.sync.aligned.m16n8k16.row.col.f32.f16.f16.f32 "
        "{%0,%1,%2,%3}, {%4,%5,%6,%7}, {%8,%9}, {%0,%1,%2,%3};"
        : "+f"(c[0]), "+f"(c[1]), "+f"(c[2]), "+f"(c[3])
        : "r"(a[0]), "r"(a[1]), "r"(a[2]), "r"(a[3]), "r"(b[0]), "r"(b[1]));
}

#define LDSM_X4(r0, r1, r2, r3, addr)                                       \
    asm volatile("ldmatrix.sync.aligned.m8n8.x4.shared.b16 {%0,%1,%2,%3}, [%4];" \
                 : "=r"(r0), "=r"(r1), "=r"(r2), "=r"(r3) : "r"(addr))

__device__ __forceinline__ void cp16(uint32_t dst, const void* src, int srcsize) {
    asm volatile("cp.async.cg.shared.global [%0], [%1], 16, %2;"
                 :: "r"(dst), "l"(src), "r"(srcsize));
}
#define CP_COMMIT()  asm volatile("cp.async.commit_group;")
#define CP_WAIT1()   asm volatile("cp.async.wait_group 1;")

__device__ __forceinline__ float silu(float x) {
    return x / (1.f + __expf(-x));
}

__device__ __forceinline__ float4 ldg4(const float* p) {
    return __ldg((const float4*)p);
}

// ---------------------------------------------------------------- prep
// Block 0: routing. Blocks 1..N-1: convert hs + gate_up to fp16.
__global__ void prep_kernel(const float* __restrict__ hs,
                            const float* __restrict__ wgu,
                            const int* __restrict__ sel) {
    const int tid = threadIdx.x;
    if (blockIdx.x == 0) {
        __shared__ int cnt[E_], cur[E_];
        if (tid < E_) cnt[tid] = 0;
        __syncthreads();
        for (int i = tid; i < T_ * K_; i += blockDim.x) {
            int e = min(max(sel[i], 0), E_ - 1);
            atomicAdd(&cnt[e], 1);
        }
        __syncthreads();
        if (tid == 0) {
            int off = 0, nt = 0;
            for (int e = 0; e < E_; e++) {
                cur[e] = off;
                for (int m = 0; m < cnt[e] && nt < MAX_TILES; m += BM) {
                    g_tile_e[nt] = e;
                    g_tile_start[nt] = off + m;
                    g_tile_cnt[nt] = min(BM, cnt[e] - m);
                    nt++;
                }
                off += cnt[e];
            }
            g_num_tiles = nt;
        }
        __syncthreads();
        for (int i = tid; i < T_ * K_; i += blockDim.x) {
            int e = min(max(sel[i], 0), E_ - 1);
            int pos = atomicAdd(&cur[e], 1);
            if (pos < T_ * K_) g_pair_src[pos] = i;
        }
        return;
    }
    const size_t stride = (size_t)(gridDim.x - 1) * blockDim.x;
    const size_t i0 = (size_t)(blockIdx.x - 1) * blockDim.x + tid;
    for (size_t q = i0; q < (size_t)T_ * H_ / 4; q += stride) {
        float4 v = ldg4(hs + 4 * q);
        *(uint2*)&g_hs_h[2 * q] = make_uint2(pack_h2(v.x, v.y), pack_h2(v.z, v.w));
    }
#pragma unroll 2
    for (size_t q = i0; q < (size_t)E_ * 2 * I_ * H_ / 4; q += stride) {
        float4 v = ldg4(wgu + 4 * q);
        *(uint2*)&g_wgu_h[2 * q] = make_uint2(pack_h2(v.x, v.y), pack_h2(v.z, v.w));
    }
}

// ---------------------------------------------------------------- GEMM1
// inter[pair, n] = silu(x.Wg^T[n]) * (x.Wu^T[n]); CTA: 128 pairs x 64 n-cols.
// Blocks with blockIdx.x >= MAX_TILES convert a slice of down_proj instead
// (overlaps the dn fp32->fp16 conversion with GEMM1 compute).
__global__ void __launch_bounds__(THREADS, 2)
gemm1_kernel(const float* __restrict__ dn) {
    const int tile = blockIdx.x;
    const int tid = threadIdx.x;
    if (tile >= MAX_TILES) {
        // dn converter CTA: 128 of them, contiguous slices of 32768 float4
        const int cid = blockIdx.y * CONV_X + (tile - MAX_TILES);   // 0..127
        const size_t per = (size_t)E_ * H_ * I_ / 4 / (16 * CONV_X);
        const size_t lo = (size_t)cid * per, hi = lo + per;
#pragma unroll 4
        for (size_t q = lo + tid; q < hi; q += THREADS) {
            float4 v = ldg4(dn + 4 * q);
            *(uint2*)&g_dn_h[2 * q] = make_uint2(pack_h2(v.x, v.y), pack_h2(v.z, v.w));
        }
        return;
    }
    if (tile >= g_num_tiles) return;
    const int nblk = blockIdx.y;                 // 0..15  (I/64)
    const int e     = g_tile_e[tile];
    const int start = g_tile_start[tile];
    const int cnt   = g_tile_cnt[tile];
    const int wid = tid >> 5, lane = tid & 31;
    const int wm = wid & 3, wn = wid >> 2;

    extern __shared__ uint32_t sm[];
    uint32_t* Asm = sm;                  // [STAGES][BM][HKP] fp16x2 words
    uint32_t* Bsm = sm + STAGES * SBW;
    __shared__ int s_tok[BM];

    if (tid < BM) {
        int v = (tid < cnt) ? g_pair_src[start + tid] : 0;
        s_tok[tid] = v / K_;
    }
    __syncthreads();

    const uint32_t* wbh = g_wgu_h + (size_t)e * (2 * I_) * (H_ / 2);

    uint32_t a_dst[4], b_dst[4];
    const uint32_t* a_src[4];
    const uint32_t* b_src[4];
    int a_sz[4];
#pragma unroll
    for (int j = 0; j < 4; j++) {
        int ia = tid + j * THREADS;
        int r = ia >> 3, q = ia & 7;
        a_dst[j] = (uint32_t)__cvta_generic_to_shared(&Asm[r * HKP + q * 4]);
        b_dst[j] = (uint32_t)__cvta_generic_to_shared(&Bsm[r * HKP + q * 4]);
        a_src[j] = g_hs_h + (size_t)s_tok[r] * (H_ / 2) + q * 4;
        int wr = (r < 64) ? (nblk * 64 + r) : (I_ + nblk * 64 + r - 64);
        b_src[j] = wbh + (size_t)wr * (H_ / 2) + q * 4;
        a_sz[j] = (r < cnt) ? 16 : 0;
    }

    const uint32_t Asm_s = (uint32_t)__cvta_generic_to_shared(Asm);
    const uint32_t Bsm_s = (uint32_t)__cvta_generic_to_shared(Bsm);
    uint32_t a_lm[2];
#pragma unroll
    for (int mb = 0; mb < 2; mb++) {
        int row = wm * 32 + mb * 16 + (lane & 15);
        a_lm[mb] = (uint32_t)((row * HKP + (lane >> 4) * 4) * 4);
    }
    uint32_t b_lm[4];
#pragma unroll
    for (int p = 0; p < 4; p++) {
        int rowbase = (p < 2) ? (wn * 32 + p * 16) : (64 + wn * 32 + (p - 2) * 16);
        int row = rowbase + (lane & 7) + ((lane >> 4) << 3);
        b_lm[p] = (uint32_t)((row * HKP + ((lane >> 3) & 1) * 4) * 4);
    }

    float acc[2][8][4];
#pragma unroll
    for (int mb = 0; mb < 2; mb++)
#pragma unroll
        for (int nb = 0; nb < 8; nb++)
#pragma unroll
            for (int i = 0; i < 4; i++) acc[mb][nb][i] = 0.f;

    const int NK = H_ / KC;          // 32 chunks
#pragma unroll
    for (int s = 0; s < STAGES - 1; s++) {
        const uint32_t boff = (uint32_t)s * SBW * 4;
#pragma unroll
        for (int j = 0; j < 4; j++) {
            cp16(a_dst[j] + boff, a_src[j] + s * 32, a_sz[j]);
            cp16(b_dst[j] + boff, b_src[j] + s * 32, 16);
        }
        CP_COMMIT();
    }

#pragma unroll 1
    for (int kk = 0; kk < NK; kk++) {
        CP_WAIT1();
        __syncthreads();
        // issue chunk kk+2 into buffer (kk-1)%3 immediately (readers of chunk
        // kk-1 all passed the barrier above), then compute chunk kk.
        const int nc = kk + STAGES - 1;
        if (nc < NK) {
            const uint32_t boff = (uint32_t)(nc % STAGES) * SBW * 4;
#pragma unroll
            for (int j = 0; j < 4; j++) {
                cp16(a_dst[j] + boff, a_src[j] + nc * 32, a_sz[j]);
                cp16(b_dst[j] + boff, b_src[j] + nc * 32, 16);
            }
        }
        CP_COMMIT();
        const uint32_t ab = Asm_s + (uint32_t)(kk % STAGES) * SBW * 4;
        const uint32_t bb = Bsm_s + (uint32_t)(kk % STAGES) * SBW * 4;
#pragma unroll
        for (int s2 = 0; s2 < 4; s2++) {                  // four k16 slabs
            const uint32_t kb = (uint32_t)(s2 * 8 * 4);
            uint32_t af[2][4];
            LDSM_X4(af[0][0], af[0][1], af[0][2], af[0][3], ab + a_lm[0] + kb);
            LDSM_X4(af[1][0], af[1][1], af[1][2], af[1][3], ab + a_lm[1] + kb);
            uint32_t bf[8][2];
#pragma unroll
            for (int p = 0; p < 4; p++)
                LDSM_X4(bf[2 * p][0], bf[2 * p][1], bf[2 * p + 1][0], bf[2 * p + 1][1],
                        bb + b_lm[p] + kb);
#pragma unroll
            for (int mb = 0; mb < 2; mb++)
#pragma unroll
                for (int nb = 0; nb < 8; nb++)
                    mma_f16(acc[mb][nb], af[mb], bf[nb]);
        }
    }

    // epilogue: silu(gate)*up -> g_inter_h
    const int g = lane >> 2, t = lane & 3;
#pragma unroll
    for (int mb = 0; mb < 2; mb++) {
        int r0 = wm * 32 + mb * 16 + g;
#pragma unroll
        for (int nb = 0; nb < 4; nb++) {
            int colw = (nblk * 64 + wn * 32 + nb * 8) / 2 + t;
            const float* cg = acc[mb][nb];
            const float* cu = acc[mb][nb + 4];
            if (r0 < cnt)
                g_inter_h[(size_t)(start + r0) * (I_ / 2) + colw] =
                    pack_h2(silu(cg[0]) * cu[0], silu(cg[1]) * cu[1]);
            if (r0 + 8 < cnt)
                g_inter_h[(size_t)(start + r0 + 8) * (I_ / 2) + colw] =
                    pack_h2(silu(cg[2]) * cu[2], silu(cg[3]) * cu[3]);
        }
    }
}

// ---------------------------------------------------------------- GEMM2
// out[src(pair), h] = inter[pair, :] . down[e, h, :]; CTA: 128 pairs x 128 h.
__global__ void __launch_bounds__(THREADS, 2)
gemm2_kernel(float* __restrict__ out) {
    const int tile = blockIdx.x;
    if (tile >= g_num_tiles) return;
    const int nblk = blockIdx.y;                 // 0..15  (H/128)
    const int e     = g_tile_e[tile];
    const int start = g_tile_start[tile];
    const int cnt   = g_tile_cnt[tile];
    const int tid = threadIdx.x, wid = tid >> 5, lane = tid & 31;
    const int wm = wid & 3, wn = wid >> 2;

    extern __shared__ uint32_t sm[];
    uint32_t* Asm = sm;
    uint32_t* Bsm = sm + STAGES * SBW;
    __shared__ int s_src[BM];

    if (tid < BM)
        s_src[tid] = (tid < cnt) ? g_pair_src[start + tid] : 0;
    __syncthreads();

    const uint32_t* wbh = g_dn_h + ((size_t)e * H_ + (size_t)nblk * 128) * (I_ / 2);

    uint32_t a_dst[4], b_dst[4];
    const uint32_t* a_src[4];
    const uint32_t* b_src[4];
    int a_sz[4];
#pragma unroll
    for (int j = 0; j < 4; j++) {
        int ia = tid + j * THREADS;
        int r = ia >> 3, q = ia & 7;
        a_dst[j] = (uint32_t)__cvta_generic_to_shared(&Asm[r * HKP + q * 4]);
        b_dst[j] = (uint32_t)__cvta_generic_to_shared(&Bsm[r * HKP + q * 4]);
        a_src[j] = g_inter_h + (size_t)(start + ((r < cnt) ? r : 0)) * (I_ / 2) + q * 4;
        b_src[j] = wbh + (size_t)r * (I_ / 2) + q * 4;
        a_sz[j] = (r < cnt) ? 16 : 0;
    }

    const uint32_t Asm_s = (uint32_t)__cvta_generic_to_shared(Asm);
    const uint32_t Bsm_s = (uint32_t)__cvta_generic_to_shared(Bsm);
    uint32_t a_lm[2];
#pragma unroll
    for (int mb = 0; mb < 2; mb++) {
        int row = wm * 32 + mb * 16 + (lane & 15);
        a_lm[mb] = (uint32_t)((row * HKP + (lane >> 4) * 4) * 4);
    }
    uint32_t b_lm[4];
#pragma unroll
    for (int p = 0; p < 4; p++) {
        int row = wn * 64 + p * 16 + (lane & 7) + ((lane >> 4) << 3);
        b_lm[p] = (uint32_t)((row * HKP + ((lane >> 3) & 1) * 4) * 4);
    }

    float acc[2][8][4];
#pragma unroll
    for (int mb = 0; mb < 2; mb++)
#pragma unroll
        for (int nb = 0; nb < 8; nb++)
#pragma unroll
            for (int i = 0; i < 4; i++) acc[mb][nb][i] = 0.f;

    const int NK = I_ / KC;          // 16 chunks
#pragma unroll
    for (int s = 0; s < STAGES - 1; s++) {
        const uint32_t boff = (uint32_t)s * SBW * 4;
#pragma unroll
        for (int j = 0; j < 4; j++) {
            cp16(a_dst[j] + boff, a_src[j] + s * 32, a_sz[j]);
            cp16(b_dst[j] + boff, b_src[j] + s * 32, 16);
        }
        CP_COMMIT();
    }

#pragma unroll 1
    for (int kk = 0; kk < NK; kk++) {
        CP_WAIT1();
        __syncthreads();
        const int nc = kk + STAGES - 1;
        if (nc < NK) {
            const uint32_t boff = (uint32_t)(nc % STAGES) * SBW * 4;
#pragma unroll
            for (int j = 0; j < 4; j++) {
                cp16(a_dst[j] + boff, a_src[j] + nc * 32, a_sz[j]);
                cp16(b_dst[j] + boff, b_src[j] + nc * 32, 16);
            }
        }
        CP_COMMIT();
        const uint32_t ab = Asm_s + (uint32_t)(kk % STAGES) * SBW * 4;
        const uint32_t bb = Bsm_s + (uint32_t)(kk % STAGES) * SBW * 4;
#pragma unroll
        for (int s2 = 0; s2 < 4; s2++) {
            const uint32_t kb = (uint32_t)(s2 * 8 * 4);
            uint32_t af[2][4];
            LDSM_X4(af[0][0], af[0][1], af[0][2], af[0][3], ab + a_lm[0] + kb);
            LDSM_X4(af[1][0], af[1][1], af[1][2], af[1][3], ab + a_lm[1] + kb);
            uint32_t bf[8][2];
#pragma unroll
            for (int p = 0; p < 4; p++)
                LDSM_X4(bf[2 * p][0], bf[2 * p][1], bf[2 * p + 1][0], bf[2 * p + 1][1],
                        bb + b_lm[p] + kb);
#pragma unroll
            for (int mb = 0; mb < 2; mb++)
#pragma unroll
                for (int nb = 0; nb < 8; nb++)
                    mma_f16(acc[mb][nb], af[mb], bf[nb]);
        }
    }

    // epilogue: scatter rows to out[src] (fp32)
    const int g = lane >> 2, t = lane & 3;
#pragma unroll
    for (int mb = 0; mb < 2; mb++) {
        int r0 = wm * 32 + mb * 16 + g;
        int src0 = s_src[r0 & (BM - 1)];
        int src1 = s_src[(r0 + 8) & (BM - 1)];
#pragma unroll
        for (int nb = 0; nb < 8; nb++) {
            int col = nblk * 128 + wn * 64 + nb * 8 + 2 * t;
            const float* c = acc[mb][nb];
            if (r0 < cnt)
                *(float2*)(out + (size_t)src0 * H_ + col) = make_float2(c[0], c[1]);
            if (r0 + 8 < cnt)
                *(float2*)(out + (size_t)src1 * H_ + col) = make_float2(c[2], c[3]);
        }
    }
}

// ---------------------------------------------------------------- launch
extern "C" void kernel_launch(void* const* d_in, const int* in_sizes, int n_in,
                              void* d_out, int out_size) {
    // Identify inputs by element count (robust to metadata ordering)
    const float* hs  = nullptr;
    const int*   sel = nullptr;
    const float* wgu = nullptr;
    const float* dn  = nullptr;
    for (int i = 0; i < n_in; i++) {
        long long n = in_sizes[i];
        if (n == (long long)T_ * H_)               hs  = (const float*)d_in[i];
        else if (n == (long long)T_ * K_)          sel = (const int*)d_in[i];
        else if (n == (long long)E_ * 2 * I_ * H_) wgu = (const float*)d_in[i];
        else if (n == (long long)E_ * H_ * I_)     dn  = (const float*)d_in[i];
    }
    float* out = (float*)d_out;
    if (!hs || !sel || !wgu || !dn) return;

    cudaFuncSetAttribute(gemm1_kernel, cudaFuncAttributeMaxDynamicSharedMemorySize, SMEM_BYTES);
    cudaFuncSetAttribute(gemm2_kernel, cudaFuncAttributeMaxDynamicSharedMemorySize, SMEM_BYTES);

    prep_kernel<<<2048, 256>>>(hs, wgu, sel);
    gemm1_kernel<<<dim3(MAX_TILES + CONV_X, I_ / 64), THREADS, SMEM_BYTES>>>(dn);
    gemm2_kernel<<<dim3(MAX_TILES, H_ / 128), THREADS, SMEM_BYTES>>>(out);
}

// round 14
// speedup vs baseline: 1.0582x; 1.0582x over previous
#include <cuda_runtime.h>
#include <cstdint>

// Problem constants
#define T_ 1024
#define K_ 2
#define E_ 8
#define H_ 2048
#define I_ 1024

#define BM 128
#define KC 64            // K chunk in elements (= 32 fp16x2 words, 128B/row)
#define HKP 36           // smem row stride in fp16x2 words (32 used + 4 pad)
#define THREADS 256
#define MAX_TILES 24
#define STAGES 3
#define SBW (BM * HKP)                       // words per tile buffer (4608)
#define SMEM_BYTES (2 * STAGES * SBW * 4)    // As + Bs = 110592 bytes

// Scratch (device globals — allocation is forbidden)
__device__ int      g_pair_src[T_ * K_];
__device__ int      g_tile_e[MAX_TILES];
__device__ int      g_tile_start[MAX_TILES];
__device__ int      g_tile_cnt[MAX_TILES];
__device__ int      g_num_tiles;
__device__ uint32_t g_hs_h[(size_t)T_ * H_ / 2];             // fp16x2
__device__ uint32_t g_wgu_h[(size_t)E_ * 2 * I_ * H_ / 2];   // fp16x2
__device__ uint32_t g_dn_h[(size_t)E_ * H_ * I_ / 2];        // fp16x2
__device__ uint32_t g_inter_h[(size_t)T_ * K_ * I_ / 2];     // fp16x2

// ---------------------------------------------------------------- helpers
__device__ __forceinline__ uint32_t pack_h2(float lo, float hi) {
    uint32_t r; asm("cvt.rn.f16x2.f32 %0, %1, %2;" : "=r"(r) : "f"(hi), "f"(lo));
    return r;
}

__device__ __forceinline__ void mma_f16(float* c, const uint32_t* a, const uint32_t* b) {
    asm volatile(
        "mma.sync.aligned.m16n8k16.row.col.f32.f16.f16.f32 "
        "{%0,%1,%2,%3}, {%4,%5,%6,%7}, {%8,%9}, {%0,%1,%2,%3};"
        : "+f"(c[0]), "+f"(c[1]), "+f"(c[2]), "+f"(c[3])
        : "r"(a[0]), "r"(a[1]), "r"(a[2]), "r"(a[3]), "r"(b[0]), "r"(b[1]));
}

#define LDSM_X4(r0, r1, r2, r3, addr)                                       \
    asm volatile("ldmatrix.sync.aligned.m8n8.x4.shared.b16 {%0,%1,%2,%3}, [%4];" \
                 : "=r"(r0), "=r"(r1), "=r"(r2), "=r"(r3) : "r"(addr))

__device__ __forceinline__ void cp16(uint32_t dst, const void* src, int srcsize) {
    asm volatile("cp.async.cg.shared.global [%0], [%1], 16, %2;"
                 :: "r"(dst), "l"(src), "r"(srcsize));
}
#define CP_COMMIT()  asm volatile("cp.async.commit_group;")
#define CP_WAIT1()   asm volatile("cp.async.wait_group 1;")

__device__ __forceinline__ float silu(float x) {
    return x / (1.f + __expf(-x));
}

__device__ __forceinline__ float4 ldg4(const float* p) {
    return __ldg((const float4*)p);
}

// ---------------------------------------------------------------- prep
// Block 0: routing. Blocks 1..N-1: convert hs + gate_up + down to fp16.
__global__ void prep_kernel(const float* __restrict__ hs,
                            const float* __restrict__ wgu,
                            const float* __restrict__ dn,
                            const int* __restrict__ sel) {
    const int tid = threadIdx.x;
    if (blockIdx.x == 0) {
        __shared__ int cnt[E_], cur[E_];
        if (tid < E_) cnt[tid] = 0;
        __syncthreads();
        for (int i = tid; i < T_ * K_; i += blockDim.x) {
            int e = min(max(sel[i], 0), E_ - 1);
            atomicAdd(&cnt[e], 1);
        }
        __syncthreads();
        if (tid == 0) {
            int off = 0, nt = 0;
            for (int e = 0; e < E_; e++) {
                cur[e] = off;
                for (int m = 0; m < cnt[e] && nt < MAX_TILES; m += BM) {
                    g_tile_e[nt] = e;
                    g_tile_start[nt] = off + m;
                    g_tile_cnt[nt] = min(BM, cnt[e] - m);
                    nt++;
                }
                off += cnt[e];
            }
            g_num_tiles = nt;
        }
        __syncthreads();
        for (int i = tid; i < T_ * K_; i += blockDim.x) {
            int e = min(max(sel[i], 0), E_ - 1);
            int pos = atomicAdd(&cur[e], 1);
            if (pos < T_ * K_) g_pair_src[pos] = i;
        }
        return;
    }
    const size_t stride = (size_t)(gridDim.x - 1) * blockDim.x;
    const size_t i0 = (size_t)(blockIdx.x - 1) * blockDim.x + tid;
    for (size_t q = i0; q < (size_t)T_ * H_ / 4; q += stride) {
        float4 v = ldg4(hs + 4 * q);
        *(uint2*)&g_hs_h[2 * q] = make_uint2(pack_h2(v.x, v.y), pack_h2(v.z, v.w));
    }
#pragma unroll 2
    for (size_t q = i0; q < (size_t)E_ * 2 * I_ * H_ / 4; q += stride) {
        float4 v = ldg4(wgu + 4 * q);
        *(uint2*)&g_wgu_h[2 * q] = make_uint2(pack_h2(v.x, v.y), pack_h2(v.z, v.w));
    }
#pragma unroll 2
    for (size_t q = i0; q < (size_t)E_ * H_ * I_ / 4; q += stride) {
        float4 v = ldg4(dn + 4 * q);
        *(uint2*)&g_dn_h[2 * q] = make_uint2(pack_h2(v.x, v.y), pack_h2(v.z, v.w));
    }
}

// ---------------------------------------------------------------- GEMM1
// inter[pair, n] = silu(x.Wg^T[n]) * (x.Wu^T[n]); CTA: 128 pairs x 64 n-cols.
// C tile 128x128: cols 0..63 = gate(nblk*64..), cols 64..127 = up(same).
__global__ void __launch_bounds__(THREADS, 2)
gemm1_kernel() {
    const int tile = blockIdx.x;
    if (tile >= g_num_tiles) return;
    const int nblk = blockIdx.y;                 // 0..15  (I/64)
    const int e     = g_tile_e[tile];
    const int start = g_tile_start[tile];
    const int cnt   = g_tile_cnt[tile];
    const int tid = threadIdx.x, wid = tid >> 5, lane = tid & 31;
    const int wm = wid & 3, wn = wid >> 2;

    extern __shared__ uint32_t sm[];
    uint32_t* Asm = sm;                  // [STAGES][BM][HKP] fp16x2 words
    uint32_t* Bsm = sm + STAGES * SBW;
    __shared__ int s_tok[BM];

    if (tid < BM) {
        int v = (tid < cnt) ? g_pair_src[start + tid] : 0;
        s_tok[tid] = v / K_;
    }
    __syncthreads();

    const uint32_t* wbh = g_wgu_h + (size_t)e * (2 * I_) * (H_ / 2);

    uint32_t a_dst[4], b_dst[4];
    const uint32_t* a_src[4];
    const uint32_t* b_src[4];
    int a_sz[4];
#pragma unroll
    for (int j = 0; j < 4; j++) {
        int ia = tid + j * THREADS;
        int r = ia >> 3, q = ia & 7;
        a_dst[j] = (uint32_t)__cvta_generic_to_shared(&Asm[r * HKP + q * 4]);
        b_dst[j] = (uint32_t)__cvta_generic_to_shared(&Bsm[r * HKP + q * 4]);
        a_src[j] = g_hs_h + (size_t)s_tok[r] * (H_ / 2) + q * 4;
        int wr = (r < 64) ? (nblk * 64 + r) : (I_ + nblk * 64 + r - 64);
        b_src[j] = wbh + (size_t)wr * (H_ / 2) + q * 4;
        a_sz[j] = (r < cnt) ? 16 : 0;
    }

    const uint32_t Asm_s = (uint32_t)__cvta_generic_to_shared(Asm);
    const uint32_t Bsm_s = (uint32_t)__cvta_generic_to_shared(Bsm);
    uint32_t a_lm[2];
#pragma unroll
    for (int mb = 0; mb < 2; mb++) {
        int row = wm * 32 + mb * 16 + (lane & 15);
        a_lm[mb] = (uint32_t)((row * HKP + (lane >> 4) * 4) * 4);
    }
    uint32_t b_lm[4];
#pragma unroll
    for (int p = 0; p < 4; p++) {
        int rowbase = (p < 2) ? (wn * 32 + p * 16) : (64 + wn * 32 + (p - 2) * 16);
        int row = rowbase + (lane & 7) + ((lane >> 4) << 3);
        b_lm[p] = (uint32_t)((row * HKP + ((lane >> 3) & 1) * 4) * 4);
    }

    float acc[2][8][4];
#pragma unroll
    for (int mb = 0; mb < 2; mb++)
#pragma unroll
        for (int nb = 0; nb < 8; nb++)
#pragma unroll
            for (int i = 0; i < 4; i++) acc[mb][nb][i] = 0.f;

    const int NK = H_ / KC;          // 32 chunks
#pragma unroll
    for (int s = 0; s < STAGES - 1; s++) {
        const uint32_t boff = (uint32_t)s * SBW * 4;
#pragma unroll
        for (int j = 0; j < 4; j++) {
            cp16(a_dst[j] + boff, a_src[j] + s * 32, a_sz[j]);
            cp16(b_dst[j] + boff, b_src[j] + s * 32, 16);
        }
        CP_COMMIT();
    }

#pragma unroll 1
    for (int kk = 0; kk < NK; kk++) {
        CP_WAIT1();
        __syncthreads();
        const uint32_t ab = Asm_s + (uint32_t)(kk % STAGES) * SBW * 4;
        const uint32_t bb = Bsm_s + (uint32_t)(kk % STAGES) * SBW * 4;
#pragma unroll
        for (int s2 = 0; s2 < 4; s2++) {                  // four k16 slabs
            const uint32_t kb = (uint32_t)(s2 * 8 * 4);
            uint32_t af[2][4];
            LDSM_X4(af[0][0], af[0][1], af[0][2], af[0][3], ab + a_lm[0] + kb);
            LDSM_X4(af[1][0], af[1][1], af[1][2], af[1][3], ab + a_lm[1] + kb);
            uint32_t bf[8][2];
#pragma unroll
            for (int p = 0; p < 4; p++)
                LDSM_X4(bf[2 * p][0], bf[2 * p][1], bf[2 * p + 1][0], bf[2 * p + 1][1],
                        bb + b_lm[p] + kb);
#pragma unroll
            for (int mb = 0; mb < 2; mb++)
#pragma unroll
                for (int nb = 0; nb < 8; nb++)
                    mma_f16(acc[mb][nb], af[mb], bf[nb]);
        }
        const int nc = kk + STAGES - 1;
        if (nc < NK) {
            const uint32_t boff = (uint32_t)(nc % STAGES) * SBW * 4;
#pragma unroll
            for (int j = 0; j < 4; j++) {
                cp16(a_dst[j] + boff, a_src[j] + nc * 32, a_sz[j]);
                cp16(b_dst[j] + boff, b_src[j] + nc * 32, 16);
            }
        }
        CP_COMMIT();
    }

    // epilogue: silu(gate)*up -> g_inter_h
    const int g = lane >> 2, t = lane & 3;
#pragma unroll
    for (int mb = 0; mb < 2; mb++) {
        int r0 = wm * 32 + mb * 16 + g;
#pragma unroll
        for (int nb = 0; nb < 4; nb++) {
            int colw = (nblk * 64 + wn * 32 + nb * 8) / 2 + t;
            const float* cg = acc[mb][nb];
            const float* cu = acc[mb][nb + 4];
            if (r0 < cnt)
                g_inter_h[(size_t)(start + r0) * (I_ / 2) + colw] =
                    pack_h2(silu(cg[0]) * cu[0], silu(cg[1]) * cu[1]);
            if (r0 + 8 < cnt)
                g_inter_h[(size_t)(start + r0 + 8) * (I_ / 2) + colw] =
                    pack_h2(silu(cg[2]) * cu[2], silu(cg[3]) * cu[3]);
        }
    }
}

// ---------------------------------------------------------------- GEMM2
// out[src(pair), h] = inter[pair, :] . down[e, h, :]; CTA: 128 pairs x 128 h.
__global__ void __launch_bounds__(THREADS, 2)
gemm2_kernel(float* __restrict__ out) {
    const int tile = blockIdx.x;
    if (tile >= g_num_tiles) return;
    const int nblk = blockIdx.y;                 // 0..15  (H/128)
    const int e     = g_tile_e[tile];
    const int start = g_tile_start[tile];
    const int cnt   = g_tile_cnt[tile];
    const int tid = threadIdx.x, wid = tid >> 5, lane = tid & 31;
    const int wm = wid & 3, wn = wid >> 2;

    extern __shared__ uint32_t sm[];
    uint32_t* Asm = sm;
    uint32_t* Bsm = sm + STAGES * SBW;
    __shared__ int s_src[BM];

    if (tid < BM)
        s_src[tid] = (tid < cnt) ? g_pair_src[start + tid] : 0;
    __syncthreads();

    const uint32_t* wbh = g_dn_h + ((size_t)e * H_ + (size_t)nblk * 128) * (I_ / 2);

    uint32_t a_dst[4], b_dst[4];
    const uint32_t* a_src[4];
    const uint32_t* b_src[4];
    int a_sz[4];
#pragma unroll
    for (int j = 0; j < 4; j++) {
        int ia = tid + j * THREADS;
        int r = ia >> 3, q = ia & 7;
        a_dst[j] = (uint32_t)__cvta_generic_to_shared(&Asm[r * HKP + q * 4]);
        b_dst[j] = (uint32_t)__cvta_generic_to_shared(&Bsm[r * HKP + q * 4]);
        a_src[j] = g_inter_h + (size_t)(start + ((r < cnt) ? r : 0)) * (I_ / 2) + q * 4;
        b_src[j] = wbh + (size_t)r * (I_ / 2) + q * 4;
        a_sz[j] = (r < cnt) ? 16 : 0;
    }

    const uint32_t Asm_s = (uint32_t)__cvta_generic_to_shared(Asm);
    const uint32_t Bsm_s = (uint32_t)__cvta_generic_to_shared(Bsm);
    uint32_t a_lm[2];
#pragma unroll
    for (int mb = 0; mb < 2; mb++) {
        int row = wm * 32 + mb * 16 + (lane & 15);
        a_lm[mb] = (uint32_t)((row * HKP + (lane >> 4) * 4) * 4);
    }
    uint32_t b_lm[4];
#pragma unroll
    for (int p = 0; p < 4; p++) {
        int row = wn * 64 + p * 16 + (lane & 7) + ((lane >> 4) << 3);
        b_lm[p] = (uint32_t)((row * HKP + ((lane >> 3) & 1) * 4) * 4);
    }

    float acc[2][8][4];
#pragma unroll
    for (int mb = 0; mb < 2; mb++)
#pragma unroll
        for (int nb = 0; nb < 8; nb++)
#pragma unroll
            for (int i = 0; i < 4; i++) acc[mb][nb][i] = 0.f;

    const int NK = I_ / KC;          // 16 chunks
#pragma unroll
    for (int s = 0; s < STAGES - 1; s++) {
        const uint32_t boff = (uint32_t)s * SBW * 4;
#pragma unroll
        for (int j = 0; j < 4; j++) {
            cp16(a_dst[j] + boff, a_src[j] + s * 32, a_sz[j]);
            cp16(b_dst[j] + boff, b_src[j] + s * 32, 16);
        }
        CP_COMMIT();
    }

#pragma unroll 1
    for (int kk = 0; kk < NK; kk++) {
        CP_WAIT1();
        __syncthreads();
        const uint32_t ab = Asm_s + (uint32_t)(kk % STAGES) * SBW * 4;
        const uint32_t bb = Bsm_s + (uint32_t)(kk % STAGES) * SBW * 4;
#pragma unroll
        for (int s2 = 0; s2 < 4; s2++) {
            const uint32_t kb = (uint32_t)(s2 * 8 * 4);
            uint32_t af[2][4];
            LDSM_X4(af[0][0], af[0][1], af[0][2], af[0][3], ab + a_lm[0] + kb);
            LDSM_X4(af[1][0], af[1][1], af[1][2], af[1][3], ab + a_lm[1] + kb);
            uint32_t bf[8][2];
#pragma unroll
            for (int p = 0; p < 4; p++)
                LDSM_X4(bf[2 * p][0], bf[2 * p][1], bf[2 * p + 1][0], bf[2 * p + 1][1],
                        bb + b_lm[p] + kb);
#pragma unroll
            for (int mb = 0; mb < 2; mb++)
#pragma unroll
                for (int nb = 0; nb < 8; nb++)
                    mma_f16(acc[mb][nb], af[mb], bf[nb]);
        }
        const int nc = kk + STAGES - 1;
        if (nc < NK) {
            const uint32_t boff = (uint32_t)(nc % STAGES) * SBW * 4;
#pragma unroll
            for (int j = 0; j < 4; j++) {
                cp16(a_dst[j] + boff, a_src[j] + nc * 32, a_sz[j]);
                cp16(b_dst[j] + boff, b_src[j] + nc * 32, 16);
            }
        }
        CP_COMMIT();
    }

    // epilogue: scatter rows to out[src] (fp32)
    const int g = lane >> 2, t = lane & 3;
#pragma unroll
    for (int mb = 0; mb < 2; mb++) {
        int r0 = wm * 32 + mb * 16 + g;
        int src0 = s_src[r0 & (BM - 1)];
        int src1 = s_src[(r0 + 8) & (BM - 1)];
#pragma unroll
        for (int nb = 0; nb < 8; nb++) {
            int col = nblk * 128 + wn * 64 + nb * 8 + 2 * t;
            const float* c = acc[mb][nb];
            if (r0 < cnt)
                *(float2*)(out + (size_t)src0 * H_ + col) = make_float2(c[0], c[1]);
            if (r0 + 8 < cnt)
                *(float2*)(out + (size_t)src1 * H_ + col) = make_float2(c[2], c[3]);
        }
    }
}

// ---------------------------------------------------------------- launch
extern "C" void kernel_launch(void* const* d_in, const int* in_sizes, int n_in,
                              void* d_out, int out_size) {
    // Identify inputs by element count (robust to metadata ordering)
    const float* hs  = nullptr;
    const int*   sel = nullptr;
    const float* wgu = nullptr;
    const float* dn  = nullptr;
    for (int i = 0; i < n_in; i++) {
        long long n = in_sizes[i];
        if (n == (long long)T_ * H_)               hs  = (const float*)d_in[i];
        else if (n == (long long)T_ * K_)          sel = (const int*)d_in[i];
        else if (n == (long long)E_ * 2 * I_ * H_) wgu = (const float*)d_in[i];
        else if (n == (long long)E_ * H_ * I_)     dn  = (const float*)d_in[i];
    }
    float* out = (float*)d_out;
    if (!hs || !sel || !wgu || !dn) return;

    cudaFuncSetAttribute(gemm1_kernel, cudaFuncAttributeMaxDynamicSharedMemorySize, SMEM_BYTES);
    cudaFuncSetAttribute(gemm2_kernel, cudaFuncAttributeMaxDynamicSharedMemorySize, SMEM_BYTES);

    prep_kernel<<<2048, 256>>>(hs, wgu, dn, sel);
    gemm1_kernel<<<dim3(MAX_TILES, I_ / 64), THREADS, SMEM_BYTES>>>();
    gemm2_kernel<<<dim3(MAX_TILES, H_ / 128), THREADS, SMEM_BYTES>>>(out);
}

// round 15
// speedup vs baseline: 1.0913x; 1.0313x over previous
#include <cuda_runtime.h>
#include <cstdint>

// Problem constants
#define T_ 1024
#define K_ 2
#define E_ 8
#define H_ 2048
#define I_ 1024

#define TILE_M 64        // pair rows per tile (halved vs R14 for wave balance)
#define BMB 128          // B tile rows in smem
#define KC 64            // K chunk in elements (= 32 fp16x2 words)
#define HKP 36           // smem row stride in fp16x2 words (32 used + 4 pad)
#define THREADS 256
#define MAX_TILES 40     // sum_e ceil(n_e/64) <= 2048/64 + 8
#define STAGES 3
#define SBW_A (TILE_M * HKP)                 // 2304 words
#define SBW_B (BMB * HKP)                    // 4608 words
#define SMEM_BYTES (STAGES * (SBW_A + SBW_B) * 4)   // 82944 bytes

// Scratch (device globals — allocation is forbidden)
__device__ int      g_pair_src[T_ * K_];
__device__ int      g_tile_e[MAX_TILES];
__device__ int      g_tile_start[MAX_TILES];
__device__ int      g_tile_cnt[MAX_TILES];
__device__ int      g_num_tiles;
__device__ uint32_t g_hs_h[(size_t)T_ * H_ / 2];             // fp16x2
__device__ uint32_t g_wgu_h[(size_t)E_ * 2 * I_ * H_ / 2];   // fp16x2
__device__ uint32_t g_dn_h[(size_t)E_ * H_ * I_ / 2];        // fp16x2
__device__ uint32_t g_inter_h[(size_t)T_ * K_ * I_ / 2];     // fp16x2

// ---------------------------------------------------------------- helpers
__device__ __forceinline__ uint32_t pack_h2(float lo, float hi) {
    uint32_t r; asm("cvt.rn.f16x2.f32 %0, %1, %2;" : "=r"(r) : "f"(hi), "f"(lo));
    return r;
}

__device__ __forceinline__ void mma_f16(float* c, const uint32_t* a, const uint32_t* b) {
    asm volatile(
        "mma.sync.aligned.m16n8k16.row.col.f32.f16.f16.f32 "
        "{%0,%1,%2,%3}, {%4,%5,%6,%7}, {%8,%9}, {%0,%1,%2,%3};"
        : "+f"(c[0]), "+f"(c[1]), "+f"(c[2]), "+f"(c[3])
        : "r"(a[0]), "r"(a[1]), "r"(a[2]), "r"(a[3]), "r"(b[0]), "r"(b[1]));
}

#define LDSM_X4(r0, r1, r2, r3, addr)                                       \
    asm volatile("ldmatrix.sync.aligned.m8n8.x4.shared.b16 {%0,%1,%2,%3}, [%4];" \
                 : "=r"(r0), "=r"(r1), "=r"(r2), "=r"(r3) : "r"(addr))

__device__ __forceinline__ void cp16(uint32_t dst, const void* src, int srcsize) {
    asm volatile("cp.async.cg.shared.global [%0], [%1], 16, %2;"
                 :: "r"(dst), "l"(src), "r"(srcsize));
}
#define CP_COMMIT()  asm volatile("cp.async.commit_group;")
#define CP_WAIT1()   asm volatile("cp.async.wait_group 1;")

__device__ __forceinline__ float silu(float x) {
    return x / (1.f + __expf(-x));
}

__device__ __forceinline__ float4 ldg4(const float* p) {
    return __ldg((const float4*)p);
}

// ---------------------------------------------------------------- prep
// Block 0: routing (64-row tiles). Blocks 1..N-1: convert hs+wgu+dn to fp16.
__global__ void prep_kernel(const float* __restrict__ hs,
                            const float* __restrict__ wgu,
                            const float* __restrict__ dn,
                            const int* __restrict__ sel) {
    const int tid = threadIdx.x;
    if (blockIdx.x == 0) {
        __shared__ int cnt[E_], cur[E_];
        if (tid < E_) cnt[tid] = 0;
        __syncthreads();
        for (int i = tid; i < T_ * K_; i += blockDim.x) {
            int e = min(max(sel[i], 0), E_ - 1);
            atomicAdd(&cnt[e], 1);
        }
        __syncthreads();
        if (tid == 0) {
            int off = 0, nt = 0;
            for (int e = 0; e < E_; e++) {
                cur[e] = off;
                for (int m = 0; m < cnt[e] && nt < MAX_TILES; m += TILE_M) {
                    g_tile_e[nt] = e;
                    g_tile_start[nt] = off + m;
                    g_tile_cnt[nt] = min(TILE_M, cnt[e] - m);
                    nt++;
                }
                off += cnt[e];
            }
            g_num_tiles = nt;
        }
        __syncthreads();
        for (int i = tid; i < T_ * K_; i += blockDim.x) {
            int e = min(max(sel[i], 0), E_ - 1);
            int pos = atomicAdd(&cur[e], 1);
            if (pos < T_ * K_) g_pair_src[pos] = i;
        }
        return;
    }
    const size_t stride = (size_t)(gridDim.x - 1) * blockDim.x;
    const size_t i0 = (size_t)(blockIdx.x - 1) * blockDim.x + tid;
    for (size_t q = i0; q < (size_t)T_ * H_ / 4; q += stride) {
        float4 v = ldg4(hs + 4 * q);
        *(uint2*)&g_hs_h[2 * q] = make_uint2(pack_h2(v.x, v.y), pack_h2(v.z, v.w));
    }
#pragma unroll 2
    for (size_t q = i0; q < (size_t)E_ * 2 * I_ * H_ / 4; q += stride) {
        float4 v = ldg4(wgu + 4 * q);
        *(uint2*)&g_wgu_h[2 * q] = make_uint2(pack_h2(v.x, v.y), pack_h2(v.z, v.w));
    }
#pragma unroll 2
    for (size_t q = i0; q < (size_t)E_ * H_ * I_ / 4; q += stride) {
        float4 v = ldg4(dn + 4 * q);
        *(uint2*)&g_dn_h[2 * q] = make_uint2(pack_h2(v.x, v.y), pack_h2(v.z, v.w));
    }
}

// ---------------------------------------------------------------- GEMM1
// inter[pair, n] = silu(x.Wg^T[n]) * (x.Wu^T[n]); CTA: 64 pairs x 64 n-cols.
// C tile 64x128: cols 0..63 = gate(nblk*64..), cols 64..127 = up(same).
// Warps 2x4: wm in {0,1} (32 rows), wn in {0..3} (16 gate + 16 up cols).
__global__ void __launch_bounds__(THREADS, 2)
gemm1_kernel() {
    const int tile = blockIdx.x;
    if (tile >= g_num_tiles) return;
    const int nblk = blockIdx.y;                 // 0..15  (I/64)
    const int e     = g_tile_e[tile];
    const int start = g_tile_start[tile];
    const int cnt   = g_tile_cnt[tile];
    const int tid = threadIdx.x, wid = tid >> 5, lane = tid & 31;
    const int wm = wid & 1, wn = wid >> 1;

    extern __shared__ uint32_t sm[];
    uint32_t* Asm = sm;                          // [STAGES][64][HKP]
    uint32_t* Bsm = sm + STAGES * SBW_A;         // [STAGES][128][HKP]
    __shared__ int s_tok[TILE_M];

    if (tid < TILE_M) {
        int v = (tid < cnt) ? g_pair_src[start + tid] : 0;
        s_tok[tid] = v / K_;
    }
    __syncthreads();

    const uint32_t* wbh = g_wgu_h + (size_t)e * (2 * I_) * (H_ / 2);

    // cp.async: A = 64 rows x 8 quads (2/thread), B = 128 rows x 8 quads (4/thread)
    uint32_t a_dst[2], b_dst[4];
    const uint32_t* a_src[2];
    const uint32_t* b_src[4];
    int a_sz[2];
#pragma unroll
    for (int j = 0; j < 2; j++) {
        int ia = tid + j * THREADS;
        int r = ia >> 3, q = ia & 7;
        a_dst[j] = (uint32_t)__cvta_generic_to_shared(&Asm[r * HKP + q * 4]);
        a_src[j] = g_hs_h + (size_t)s_tok[r] * (H_ / 2) + q * 4;
        a_sz[j] = (r < cnt) ? 16 : 0;
    }
#pragma unroll
    for (int j = 0; j < 4; j++) {
        int ia = tid + j * THREADS;
        int r = ia >> 3, q = ia & 7;
        b_dst[j] = (uint32_t)__cvta_generic_to_shared(&Bsm[r * HKP + q * 4]);
        int wr = (r < 64) ? (nblk * 64 + r) : (I_ + nblk * 64 + r - 64);
        b_src[j] = wbh + (size_t)wr * (H_ / 2) + q * 4;
    }

    const uint32_t Asm_s = (uint32_t)__cvta_generic_to_shared(Asm);
    const uint32_t Bsm_s = (uint32_t)__cvta_generic_to_shared(Bsm);
    uint32_t a_lm[2];
#pragma unroll
    for (int mb = 0; mb < 2; mb++) {
        int row = wm * 32 + mb * 16 + (lane & 15);
        a_lm[mb] = (uint32_t)((row * HKP + (lane >> 4) * 4) * 4);
    }
    uint32_t b_lm[2];
#pragma unroll
    for (int p = 0; p < 2; p++) {
        int rowbase = p * 64 + wn * 16;          // p=0 gate, p=1 up
        int row = rowbase + (lane & 7) + ((lane >> 4) << 3);
        b_lm[p] = (uint32_t)((row * HKP + ((lane >> 3) & 1) * 4) * 4);
    }

    float acc[2][4][4];
#pragma unroll
    for (int mb = 0; mb < 2; mb++)
#pragma unroll
        for (int nb = 0; nb < 4; nb++)
#pragma unroll
            for (int i = 0; i < 4; i++) acc[mb][nb][i] = 0.f;

    const int NK = H_ / KC;          // 32 chunks
#pragma unroll
    for (int s = 0; s < STAGES - 1; s++) {
        const uint32_t aoff = (uint32_t)s * SBW_A * 4;
        const uint32_t boff = (uint32_t)s * SBW_B * 4;
#pragma unroll
        for (int j = 0; j < 2; j++) cp16(a_dst[j] + aoff, a_src[j] + s * 32, a_sz[j]);
#pragma unroll
        for (int j = 0; j < 4; j++) cp16(b_dst[j] + boff, b_src[j] + s * 32, 16);
        CP_COMMIT();
    }

#pragma unroll 1
    for (int kk = 0; kk < NK; kk++) {
        CP_WAIT1();
        __syncthreads();
        // issue chunk kk+2 into buffer (kk-1)%3 (readers passed the barrier)
        const int nc = kk + STAGES - 1;
        if (nc < NK) {
            const uint32_t aoff = (uint32_t)(nc % STAGES) * SBW_A * 4;
            const uint32_t boff = (uint32_t)(nc % STAGES) * SBW_B * 4;
#pragma unroll
            for (int j = 0; j < 2; j++) cp16(a_dst[j] + aoff, a_src[j] + nc * 32, a_sz[j]);
#pragma unroll
            for (int j = 0; j < 4; j++) cp16(b_dst[j] + boff, b_src[j] + nc * 32, 16);
        }
        CP_COMMIT();
        const uint32_t ab = Asm_s + (uint32_t)(kk % STAGES) * SBW_A * 4;
        const uint32_t bb = Bsm_s + (uint32_t)(kk % STAGES) * SBW_B * 4;
#pragma unroll
        for (int s2 = 0; s2 < 4; s2++) {                  // four k16 slabs
            const uint32_t kb = (uint32_t)(s2 * 8 * 4);
            uint32_t af[2][4];
            LDSM_X4(af[0][0], af[0][1], af[0][2], af[0][3], ab + a_lm[0] + kb);
            LDSM_X4(af[1][0], af[1][1], af[1][2], af[1][3], ab + a_lm[1] + kb);
            uint32_t bf[4][2];
#pragma unroll
            for (int p = 0; p < 2; p++)
                LDSM_X4(bf[2 * p][0], bf[2 * p][1], bf[2 * p + 1][0], bf[2 * p + 1][1],
                        bb + b_lm[p] + kb);
#pragma unroll
            for (int mb = 0; mb < 2; mb++)
#pragma unroll
                for (int nb = 0; nb < 4; nb++)
                    mma_f16(acc[mb][nb], af[mb], bf[nb]);
        }
    }

    // epilogue: silu(gate)*up -> g_inter_h (gate = nb 0..1, up = nb 2..3)
    const int g = lane >> 2, t = lane & 3;
#pragma unroll
    for (int mb = 0; mb < 2; mb++) {
        int r0 = wm * 32 + mb * 16 + g;
#pragma unroll
        for (int nb = 0; nb < 2; nb++) {
            int colw = (nblk * 64 + wn * 16 + nb * 8) / 2 + t;
            const float* cg = acc[mb][nb];
            const float* cu = acc[mb][nb + 2];
            if (r0 < cnt)
                g_inter_h[(size_t)(start + r0) * (I_ / 2) + colw] =
                    pack_h2(silu(cg[0]) * cu[0], silu(cg[1]) * cu[1]);
            if (r0 + 8 < cnt)
                g_inter_h[(size_t)(start + r0 + 8) * (I_ / 2) + colw] =
                    pack_h2(silu(cg[2]) * cu[2], silu(cg[3]) * cu[3]);
        }
    }
}

// ---------------------------------------------------------------- GEMM2
// out[src(pair), h] = inter[pair, :] . down[e, h, :]; CTA: 64 pairs x 128 h.
// Warps 2x4: wm rows 32, wn covers 32 h-cols.
__global__ void __launch_bounds__(THREADS, 2)
gemm2_kernel(float* __restrict__ out) {
    const int tile = blockIdx.x;
    if (tile >= g_num_tiles) return;
    const int nblk = blockIdx.y;                 // 0..15  (H/128)
    const int e     = g_tile_e[tile];
    const int start = g_tile_start[tile];
    const int cnt   = g_tile_cnt[tile];
    const int tid = threadIdx.x, wid = tid >> 5, lane = tid & 31;
    const int wm = wid & 1, wn = wid >> 1;

    extern __shared__ uint32_t sm[];
    uint32_t* Asm = sm;
    uint32_t* Bsm = sm + STAGES * SBW_A;
    __shared__ int s_src[TILE_M];

    if (tid < TILE_M)
        s_src[tid] = (tid < cnt) ? g_pair_src[start + tid] : 0;
    __syncthreads();

    const uint32_t* wbh = g_dn_h + ((size_t)e * H_ + (size_t)nblk * 128) * (I_ / 2);

    uint32_t a_dst[2], b_dst[4];
    const uint32_t* a_src[2];
    const uint32_t* b_src[4];
    int a_sz[2];
#pragma unroll
    for (int j = 0; j < 2; j++) {
        int ia = tid + j * THREADS;
        int r = ia >> 3, q = ia & 7;
        a_dst[j] = (uint32_t)__cvta_generic_to_shared(&Asm[r * HKP + q * 4]);
        a_src[j] = g_inter_h + (size_t)(start + ((r < cnt) ? r : 0)) * (I_ / 2) + q * 4;
        a_sz[j] = (r < cnt) ? 16 : 0;
    }
#pragma unroll
    for (int j = 0; j < 4; j++) {
        int ia = tid + j * THREADS;
        int r = ia >> 3, q = ia & 7;
        b_dst[j] = (uint32_t)__cvta_generic_to_shared(&Bsm[r * HKP + q * 4]);
        b_src[j] = wbh + (size_t)r * (I_ / 2) + q * 4;
    }

    const uint32_t Asm_s = (uint32_t)__cvta_generic_to_shared(Asm);
    const uint32_t Bsm_s = (uint32_t)__cvta_generic_to_shared(Bsm);
    uint32_t a_lm[2];
#pragma unroll
    for (int mb = 0; mb < 2; mb++) {
        int row = wm * 32 + mb * 16 + (lane & 15);
        a_lm[mb] = (uint32_t)((row * HKP + (lane >> 4) * 4) * 4);
    }
    uint32_t b_lm[2];
#pragma unroll
    for (int p = 0; p < 2; p++) {
        int row = wn * 32 + p * 16 + (lane & 7) + ((lane >> 4) << 3);
        b_lm[p] = (uint32_t)((row * HKP + ((lane >> 3) & 1) * 4) * 4);
    }

    float acc[2][4][4];
#pragma unroll
    for (int mb = 0; mb < 2; mb++)
#pragma unroll
        for (int nb = 0; nb < 4; nb++)
#pragma unroll
            for (int i = 0; i < 4; i++) acc[mb][nb][i] = 0.f;

    const int NK = I_ / KC;          // 16 chunks
#pragma unroll
    for (int s = 0; s < STAGES - 1; s++) {
        const uint32_t aoff = (uint32_t)s * SBW_A * 4;
        const uint32_t boff = (uint32_t)s * SBW_B * 4;
#pragma unroll
        for (int j = 0; j < 2; j++) cp16(a_dst[j] + aoff, a_src[j] + s * 32, a_sz[j]);
#pragma unroll
        for (int j = 0; j < 4; j++) cp16(b_dst[j] + boff, b_src[j] + s * 32, 16);
        CP_COMMIT();
    }

#pragma unroll 1
    for (int kk = 0; kk < NK; kk++) {
        CP_WAIT1();
        __syncthreads();
        const int nc = kk + STAGES - 1;
        if (nc < NK) {
            const uint32_t aoff = (uint32_t)(nc % STAGES) * SBW_A * 4;
            const uint32_t boff = (uint32_t)(nc % STAGES) * SBW_B * 4;
#pragma unroll
            for (int j = 0; j < 2; j++) cp16(a_dst[j] + aoff, a_src[j] + nc * 32, a_sz[j]);
#pragma unroll
            for (int j = 0; j < 4; j++) cp16(b_dst[j] + boff, b_src[j] + nc * 32, 16);
        }
        CP_COMMIT();
        const uint32_t ab = Asm_s + (uint32_t)(kk % STAGES) * SBW_A * 4;
        const uint32_t bb = Bsm_s + (uint32_t)(kk % STAGES) * SBW_B * 4;
#pragma unroll
        for (int s2 = 0; s2 < 4; s2++) {
            const uint32_t kb = (uint32_t)(s2 * 8 * 4);
            uint32_t af[2][4];
            LDSM_X4(af[0][0], af[0][1], af[0][2], af[0][3], ab + a_lm[0] + kb);
            LDSM_X4(af[1][0], af[1][1], af[1][2], af[1][3], ab + a_lm[1] + kb);
            uint32_t bf[4][2];
#pragma unroll
            for (int p = 0; p < 2; p++)
                LDSM_X4(bf[2 * p][0], bf[2 * p][1], bf[2 * p + 1][0], bf[2 * p + 1][1],
                        bb + b_lm[p] + kb);
#pragma unroll
            for (int mb = 0; mb < 2; mb++)
#pragma unroll
                for (int nb = 0; nb < 4; nb++)
                    mma_f16(acc[mb][nb], af[mb], bf[nb]);
        }
    }

    // epilogue: scatter rows to out[src] (fp32)
    const int g = lane >> 2, t = lane & 3;
#pragma unroll
    for (int mb = 0; mb < 2; mb++) {
        int r0 = wm * 32 + mb * 16 + g;
        int src0 = s_src[r0 & (TILE_M - 1)];
        int src1 = s_src[(r0 + 8) & (TILE_M - 1)];
#pragma unroll
        for (int nb = 0; nb < 4; nb++) {
            int col = nblk * 128 + wn * 32 + nb * 8 + 2 * t;
            const float* c = acc[mb][nb];
            if (r0 < cnt)
                *(float2*)(out + (size_t)src0 * H_ + col) = make_float2(c[0], c[1]);
            if (r0 + 8 < cnt)
                *(float2*)(out + (size_t)src1 * H_ + col) = make_float2(c[2], c[3]);
        }
    }
}

// ---------------------------------------------------------------- launch
extern "C" void kernel_launch(void* const* d_in, const int* in_sizes, int n_in,
                              void* d_out, int out_size) {
    // Identify inputs by element count (robust to metadata ordering)
    const float* hs  = nullptr;
    const int*   sel = nullptr;
    const float* wgu = nullptr;
    const float* dn  = nullptr;
    for (int i = 0; i < n_in; i++) {
        long long n = in_sizes[i];
        if (n == (long long)T_ * H_)               hs  = (const float*)d_in[i];
        else if (n == (long long)T_ * K_)          sel = (const int*)d_in[i];
        else if (n == (long long)E_ * 2 * I_ * H_) wgu = (const float*)d_in[i];
        else if (n == (long long)E_ * H_ * I_)     dn  = (const float*)d_in[i];
    }
    float* out = (float*)d_out;
    if (!hs || !sel || !wgu || !dn) return;

    cudaFuncSetAttribute(gemm1_kernel, cudaFuncAttributeMaxDynamicSharedMemorySize, SMEM_BYTES);
    cudaFuncSetAttribute(gemm2_kernel, cudaFuncAttributeMaxDynamicSharedMemorySize, SMEM_BYTES);

    prep_kernel<<<2048, 256>>>(hs, wgu, dn, sel);
    gemm1_kernel<<<dim3(MAX_TILES, I_ / 64), THREADS, SMEM_BYTES>>>();
    gemm2_kernel<<<dim3(MAX_TILES, H_ / 128), THREADS, SMEM_BYTES>>>(out);
}

// round 16
// speedup vs baseline: 1.1031x; 1.0108x over previous
#include <cuda_runtime.h>
#include <cstdint>

// Problem constants
#define T_ 1024
#define K_ 2
#define E_ 8
#define H_ 2048
#define I_ 1024

#define TILE_M 64        // pair rows per tile
#define BMB 128          // B tile rows in smem
#define KC 64            // K chunk in elements (= 32 fp16x2 words)
#define HKP 36           // smem row stride in fp16x2 words (32 used + 4 pad)
#define THREADS 256
#define MAX_TILES 40     // sum_e ceil(n_e/64) <= 2048/64 + 8
#define STAGES 4
#define SBW_A (TILE_M * HKP)                 // 2304 words
#define SBW_B (BMB * HKP)                    // 4608 words
#define SMEM_BYTES (STAGES * (SBW_A + SBW_B) * 4)   // 110592 bytes

// Scratch (device globals — allocation is forbidden)
__device__ int      g_pair_src[T_ * K_];
__device__ int      g_tile_e[MAX_TILES];
__device__ int      g_tile_start[MAX_TILES];
__device__ int      g_tile_cnt[MAX_TILES];
__device__ int      g_num_tiles;
__device__ uint32_t g_hs_h[(size_t)T_ * H_ / 2];             // fp16x2
__device__ uint32_t g_wgu_h[(size_t)E_ * 2 * I_ * H_ / 2];   // fp16x2
__device__ uint32_t g_dn_h[(size_t)E_ * H_ * I_ / 2];        // fp16x2
__device__ uint32_t g_inter_h[(size_t)T_ * K_ * I_ / 2];     // fp16x2

// ---------------------------------------------------------------- helpers
__device__ __forceinline__ uint32_t pack_h2(float lo, float hi) {
    uint32_t r; asm("cvt.rn.f16x2.f32 %0, %1, %2;" : "=r"(r) : "f"(hi), "f"(lo));
    return r;
}

__device__ __forceinline__ void mma_f16(float* c, const uint32_t* a, const uint32_t* b) {
    asm volatile(
        "mma.sync.aligned.m16n8k16.row.col.f32.f16.f16.f32 "
        "{%0,%1,%2,%3}, {%4,%5,%6,%7}, {%8,%9}, {%0,%1,%2,%3};"
        : "+f"(c[0]), "+f"(c[1]), "+f"(c[2]), "+f"(c[3])
        : "r"(a[0]), "r"(a[1]), "r"(a[2]), "r"(a[3]), "r"(b[0]), "r"(b[1]));
}

#define LDSM_X4(r0, r1, r2, r3, addr)                                       \
    asm volatile("ldmatrix.sync.aligned.m8n8.x4.shared.b16 {%0,%1,%2,%3}, [%4];" \
                 : "=r"(r0), "=r"(r1), "=r"(r2), "=r"(r3) : "r"(addr))

__device__ __forceinline__ void cp16(uint32_t dst, const void* src, int srcsize) {
    asm volatile("cp.async.cg.shared.global [%0], [%1], 16, %2;"
                 :: "r"(dst), "l"(src), "r"(srcsize));
}
#define CP_COMMIT()  asm volatile("cp.async.commit_group;")
#define CP_WAIT2()   asm volatile("cp.async.wait_group 2;")

__device__ __forceinline__ float silu(float x) {
    return x / (1.f + __expf(-x));
}

__device__ __forceinline__ float4 ldg4(const float* p) {
    return __ldg((const float4*)p);
}

// ---------------------------------------------------------------- prep
// Block 0: routing (64-row tiles). Blocks 1..N-1: convert hs+wgu+dn to fp16.
__global__ void prep_kernel(const float* __restrict__ hs,
                            const float* __restrict__ wgu,
                            const float* __restrict__ dn,
                            const int* __restrict__ sel) {
    const int tid = threadIdx.x;
    if (blockIdx.x == 0) {
        __shared__ int cnt[E_], cur[E_];
        if (tid < E_) cnt[tid] = 0;
        __syncthreads();
        for (int i = tid; i < T_ * K_; i += blockDim.x) {
            int e = min(max(sel[i], 0), E_ - 1);
            atomicAdd(&cnt[e], 1);
        }
        __syncthreads();
        if (tid == 0) {
            int off = 0, nt = 0;
            for (int e = 0; e < E_; e++) {
                cur[e] = off;
                for (int m = 0; m < cnt[e] && nt < MAX_TILES; m += TILE_M) {
                    g_tile_e[nt] = e;
                    g_tile_start[nt] = off + m;
                    g_tile_cnt[nt] = min(TILE_M, cnt[e] - m);
                    nt++;
                }
                off += cnt[e];
            }
            g_num_tiles = nt;
        }
        __syncthreads();
        for (int i = tid; i < T_ * K_; i += blockDim.x) {
            int e = min(max(sel[i], 0), E_ - 1);
            int pos = atomicAdd(&cur[e], 1);
            if (pos < T_ * K_) g_pair_src[pos] = i;
        }
        return;
    }
    const size_t stride = (size_t)(gridDim.x - 1) * blockDim.x;
    const size_t i0 = (size_t)(blockIdx.x - 1) * blockDim.x + tid;
    for (size_t q = i0; q < (size_t)T_ * H_ / 4; q += stride) {
        float4 v = ldg4(hs + 4 * q);
        *(uint2*)&g_hs_h[2 * q] = make_uint2(pack_h2(v.x, v.y), pack_h2(v.z, v.w));
    }
#pragma unroll 2
    for (size_t q = i0; q < (size_t)E_ * 2 * I_ * H_ / 4; q += stride) {
        float4 v = ldg4(wgu + 4 * q);
        *(uint2*)&g_wgu_h[2 * q] = make_uint2(pack_h2(v.x, v.y), pack_h2(v.z, v.w));
    }
#pragma unroll 2
    for (size_t q = i0; q < (size_t)E_ * H_ * I_ / 4; q += stride) {
        float4 v = ldg4(dn + 4 * q);
        *(uint2*)&g_dn_h[2 * q] = make_uint2(pack_h2(v.x, v.y), pack_h2(v.z, v.w));
    }
}

// ---------------------------------------------------------------- GEMM1
// inter[pair, n] = silu(x.Wg^T[n]) * (x.Wu^T[n]); CTA: 64 pairs x 64 n-cols.
// C tile 64x128: cols 0..63 = gate(nblk*64..), cols 64..127 = up(same).
// Warps 2x4: wm in {0,1} (32 rows), wn in {0..3} (16 gate + 16 up cols).
__global__ void __launch_bounds__(THREADS, 2)
gemm1_kernel() {
    const int tile = blockIdx.x;
    if (tile >= g_num_tiles) return;
    const int nblk = blockIdx.y;                 // 0..15  (I/64)
    const int e     = g_tile_e[tile];
    const int start = g_tile_start[tile];
    const int cnt   = g_tile_cnt[tile];
    const int tid = threadIdx.x, wid = tid >> 5, lane = tid & 31;
    const int wm = wid & 1, wn = wid >> 1;

    extern __shared__ uint32_t sm[];
    uint32_t* Asm = sm;                          // [STAGES][64][HKP]
    uint32_t* Bsm = sm + STAGES * SBW_A;         // [STAGES][128][HKP]
    __shared__ int s_tok[TILE_M];

    if (tid < TILE_M) {
        int v = (tid < cnt) ? g_pair_src[start + tid] : 0;
        s_tok[tid] = v / K_;
    }
    __syncthreads();

    const uint32_t* wbh = g_wgu_h + (size_t)e * (2 * I_) * (H_ / 2);

    uint32_t a_dst[2], b_dst[4];
    const uint32_t* a_src[2];
    const uint32_t* b_src[4];
    int a_sz[2];
#pragma unroll
    for (int j = 0; j < 2; j++) {
        int ia = tid + j * THREADS;
        int r = ia >> 3, q = ia & 7;
        a_dst[j] = (uint32_t)__cvta_generic_to_shared(&Asm[r * HKP + q * 4]);
        a_src[j] = g_hs_h + (size_t)s_tok[r] * (H_ / 2) + q * 4;
        a_sz[j] = (r < cnt) ? 16 : 0;
    }
#pragma unroll
    for (int j = 0; j < 4; j++) {
        int ia = tid + j * THREADS;
        int r = ia >> 3, q = ia & 7;
        b_dst[j] = (uint32_t)__cvta_generic_to_shared(&Bsm[r * HKP + q * 4]);
        int wr = (r < 64) ? (nblk * 64 + r) : (I_ + nblk * 64 + r - 64);
        b_src[j] = wbh + (size_t)wr * (H_ / 2) + q * 4;
    }

    const uint32_t Asm_s = (uint32_t)__cvta_generic_to_shared(Asm);
    const uint32_t Bsm_s = (uint32_t)__cvta_generic_to_shared(Bsm);
    uint32_t a_lm[2];
#pragma unroll
    for (int mb = 0; mb < 2; mb++) {
        int row = wm * 32 + mb * 16 + (lane & 15);
        a_lm[mb] = (uint32_t)((row * HKP + (lane >> 4) * 4) * 4);
    }
    uint32_t b_lm[2];
#pragma unroll
    for (int p = 0; p < 2; p++) {
        int rowbase = p * 64 + wn * 16;          // p=0 gate, p=1 up
        int row = rowbase + (lane & 7) + ((lane >> 4) << 3);
        b_lm[p] = (uint32_t)((row * HKP + ((lane >> 3) & 1) * 4) * 4);
    }

    float acc[2][4][4];
#pragma unroll
    for (int mb = 0; mb < 2; mb++)
#pragma unroll
        for (int nb = 0; nb < 4; nb++)
#pragma unroll
            for (int i = 0; i < 4; i++) acc[mb][nb][i] = 0.f;

    const int NK = H_ / KC;          // 32 chunks
#pragma unroll
    for (int s = 0; s < STAGES - 1; s++) {
        const uint32_t aoff = (uint32_t)s * SBW_A * 4;
        const uint32_t boff = (uint32_t)s * SBW_B * 4;
#pragma unroll
        for (int j = 0; j < 2; j++) cp16(a_dst[j] + aoff, a_src[j] + s * 32, a_sz[j]);
#pragma unroll
        for (int j = 0; j < 4; j++) cp16(b_dst[j] + boff, b_src[j] + s * 32, 16);
        CP_COMMIT();
    }

#pragma unroll 1
    for (int kk = 0; kk < NK; kk++) {
        CP_WAIT2();
        __syncthreads();
        // issue chunk kk+3 into buffer (kk+3)%4 == (kk-1)%4 (readers of chunk
        // kk-1 all passed the barrier above)
        const int nc = kk + STAGES - 1;
        if (nc < NK) {
            const uint32_t aoff = (uint32_t)(nc % STAGES) * SBW_A * 4;
            const uint32_t boff = (uint32_t)(nc % STAGES) * SBW_B * 4;
#pragma unroll
            for (int j = 0; j < 2; j++) cp16(a_dst[j] + aoff, a_src[j] + nc * 32, a_sz[j]);
#pragma unroll
            for (int j = 0; j < 4; j++) cp16(b_dst[j] + boff, b_src[j] + nc * 32, 16);
        }
        CP_COMMIT();
        const uint32_t ab = Asm_s + (uint32_t)(kk % STAGES) * SBW_A * 4;
        const uint32_t bb = Bsm_s + (uint32_t)(kk % STAGES) * SBW_B * 4;
#pragma unroll
        for (int s2 = 0; s2 < 4; s2++) {                  // four k16 slabs
            const uint32_t kb = (uint32_t)(s2 * 8 * 4);
            uint32_t af[2][4];
            LDSM_X4(af[0][0], af[0][1], af[0][2], af[0][3], ab + a_lm[0] + kb);
            LDSM_X4(af[1][0], af[1][1], af[1][2], af[1][3], ab + a_lm[1] + kb);
            uint32_t bf[4][2];
#pragma unroll
            for (int p = 0; p < 2; p++)
                LDSM_X4(bf[2 * p][0], bf[2 * p][1], bf[2 * p + 1][0], bf[2 * p + 1][1],
                        bb + b_lm[p] + kb);
#pragma unroll
            for (int mb = 0; mb < 2; mb++)
#pragma unroll
                for (int nb = 0; nb < 4; nb++)
                    mma_f16(acc[mb][nb], af[mb], bf[nb]);
        }
    }

    // epilogue: silu(gate)*up -> g_inter_h (gate = nb 0..1, up = nb 2..3)
    const int g = lane >> 2, t = lane & 3;
#pragma unroll
    for (int mb = 0; mb < 2; mb++) {
        int r0 = wm * 32 + mb * 16 + g;
#pragma unroll
        for (int nb = 0; nb < 2; nb++) {
            int colw = (nblk * 64 + wn * 16 + nb * 8) / 2 + t;
            const float* cg = acc[mb][nb];
            const float* cu = acc[mb][nb + 2];
            if (r0 < cnt)
                g_inter_h[(size_t)(start + r0) * (I_ / 2) + colw] =
                    pack_h2(silu(cg[0]) * cu[0], silu(cg[1]) * cu[1]);
            if (r0 + 8 < cnt)
                g_inter_h[(size_t)(start + r0 + 8) * (I_ / 2) + colw] =
                    pack_h2(silu(cg[2]) * cu[2], silu(cg[3]) * cu[3]);
        }
    }
}

// ---------------------------------------------------------------- GEMM2
// out[src(pair), h] = inter[pair, :] . down[e, h, :]; CTA: 64 pairs x 128 h.
// Warps 2x4: wm rows 32, wn covers 32 h-cols.
__global__ void __launch_bounds__(THREADS, 2)
gemm2_kernel(float* __restrict__ out) {
    const int tile = blockIdx.x;
    if (tile >= g_num_tiles) return;
    const int nblk = blockIdx.y;                 // 0..15  (H/128)
    const int e     = g_tile_e[tile];
    const int start = g_tile_start[tile];
    const int cnt   = g_tile_cnt[tile];
    const int tid = threadIdx.x, wid = tid >> 5, lane = tid & 31;
    const int wm = wid & 1, wn = wid >> 1;

    extern __shared__ uint32_t sm[];
    uint32_t* Asm = sm;
    uint32_t* Bsm = sm + STAGES * SBW_A;
    __shared__ int s_src[TILE_M];

    if (tid < TILE_M)
        s_src[tid] = (tid < cnt) ? g_pair_src[start + tid] : 0;
    __syncthreads();

    const uint32_t* wbh = g_dn_h + ((size_t)e * H_ + (size_t)nblk * 128) * (I_ / 2);

    uint32_t a_dst[2], b_dst[4];
    const uint32_t* a_src[2];
    const uint32_t* b_src[4];
    int a_sz[2];
#pragma unroll
    for (int j = 0; j < 2; j++) {
        int ia = tid + j * THREADS;
        int r = ia >> 3, q = ia & 7;
        a_dst[j] = (uint32_t)__cvta_generic_to_shared(&Asm[r * HKP + q * 4]);
        a_src[j] = g_inter_h + (size_t)(start + ((r < cnt) ? r : 0)) * (I_ / 2) + q * 4;
        a_sz[j] = (r < cnt) ? 16 : 0;
    }
#pragma unroll
    for (int j = 0; j < 4; j++) {
        int ia = tid + j * THREADS;
        int r = ia >> 3, q = ia & 7;
        b_dst[j] = (uint32_t)__cvta_generic_to_shared(&Bsm[r * HKP + q * 4]);
        b_src[j] = wbh + (size_t)r * (I_ / 2) + q * 4;
    }

    const uint32_t Asm_s = (uint32_t)__cvta_generic_to_shared(Asm);
    const uint32_t Bsm_s = (uint32_t)__cvta_generic_to_shared(Bsm);
    uint32_t a_lm[2];
#pragma unroll
    for (int mb = 0; mb < 2; mb++) {
        int row = wm * 32 + mb * 16 + (lane & 15);
        a_lm[mb] = (uint32_t)((row * HKP + (lane >> 4) * 4) * 4);
    }
    uint32_t b_lm[2];
#pragma unroll
    for (int p = 0; p < 2; p++) {
        int row = wn * 32 + p * 16 + (lane & 7) + ((lane >> 4) << 3);
        b_lm[p] = (uint32_t)((row * HKP + ((lane >> 3) & 1) * 4) * 4);
    }

    float acc[2][4][4];
#pragma unroll
    for (int mb = 0; mb < 2; mb++)
#pragma unroll
        for (int nb = 0; nb < 4; nb++)
#pragma unroll
            for (int i = 0; i < 4; i++) acc[mb][nb][i] = 0.f;

    const int NK = I_ / KC;          // 16 chunks
#pragma unroll
    for (int s = 0; s < STAGES - 1; s++) {
        const uint32_t aoff = (uint32_t)s * SBW_A * 4;
        const uint32_t boff = (uint32_t)s * SBW_B * 4;
#pragma unroll
        for (int j = 0; j < 2; j++) cp16(a_dst[j] + aoff, a_src[j] + s * 32, a_sz[j]);
#pragma unroll
        for (int j = 0; j < 4; j++) cp16(b_dst[j] + boff, b_src[j] + s * 32, 16);
        CP_COMMIT();
    }

#pragma unroll 1
    for (int kk = 0; kk < NK; kk++) {
        CP_WAIT2();
        __syncthreads();
        const int nc = kk + STAGES - 1;
        if (nc < NK) {
            const uint32_t aoff = (uint32_t)(nc % STAGES) * SBW_A * 4;
            const uint32_t boff = (uint32_t)(nc % STAGES) * SBW_B * 4;
#pragma unroll
            for (int j = 0; j < 2; j++) cp16(a_dst[j] + aoff, a_src[j] + nc * 32, a_sz[j]);
#pragma unroll
            for (int j = 0; j < 4; j++) cp16(b_dst[j] + boff, b_src[j] + nc * 32, 16);
        }
        CP_COMMIT();
        const uint32_t ab = Asm_s + (uint32_t)(kk % STAGES) * SBW_A * 4;
        const uint32_t bb = Bsm_s + (uint32_t)(kk % STAGES) * SBW_B * 4;
#pragma unroll
        for (int s2 = 0; s2 < 4; s2++) {
            const uint32_t kb = (uint32_t)(s2 * 8 * 4);
            uint32_t af[2][4];
            LDSM_X4(af[0][0], af[0][1], af[0][2], af[0][3], ab + a_lm[0] + kb);
            LDSM_X4(af[1][0], af[1][1], af[1][2], af[1][3], ab + a_lm[1] + kb);
            uint32_t bf[4][2];
#pragma unroll
            for (int p = 0; p < 2; p++)
                LDSM_X4(bf[2 * p][0], bf[2 * p][1], bf[2 * p + 1][0], bf[2 * p + 1][1],
                        bb + b_lm[p] + kb);
#pragma unroll
            for (int mb = 0; mb < 2; mb++)
#pragma unroll
                for (int nb = 0; nb < 4; nb++)
                    mma_f16(acc[mb][nb], af[mb], bf[nb]);
        }
    }

    // epilogue: scatter rows to out[src] (fp32)
    const int g = lane >> 2, t = lane & 3;
#pragma unroll
    for (int mb = 0; mb < 2; mb++) {
        int r0 = wm * 32 + mb * 16 + g;
        int src0 = s_src[r0 & (TILE_M - 1)];
        int src1 = s_src[(r0 + 8) & (TILE_M - 1)];
#pragma unroll
        for (int nb = 0; nb < 4; nb++) {
            int col = nblk * 128 + wn * 32 + nb * 8 + 2 * t;
            const float* c = acc[mb][nb];
            if (r0 < cnt)
                *(float2*)(out + (size_t)src0 * H_ + col) = make_float2(c[0], c[1]);
            if (r0 + 8 < cnt)
                *(float2*)(out + (size_t)src1 * H_ + col) = make_float2(c[2], c[3]);
        }
    }
}

// ---------------------------------------------------------------- launch
extern "C" void kernel_launch(void* const* d_in, const int* in_sizes, int n_in,
                              void* d_out, int out_size) {
    // Identify inputs by element count (robust to metadata ordering)
    const float* hs  = nullptr;
    const int*   sel = nullptr;
    const float* wgu = nullptr;
    const float* dn  = nullptr;
    for (int i = 0; i < n_in; i++) {
        long long n = in_sizes[i];
        if (n == (long long)T_ * H_)               hs  = (const float*)d_in[i];
        else if (n == (long long)T_ * K_)          sel = (const int*)d_in[i];
        else if (n == (long long)E_ * 2 * I_ * H_) wgu = (const float*)d_in[i];
        else if (n == (long long)E_ * H_ * I_)     dn  = (const float*)d_in[i];
    }
    float* out = (float*)d_out;
    if (!hs || !sel || !wgu || !dn) return;

    cudaFuncSetAttribute(gemm1_kernel, cudaFuncAttributeMaxDynamicSharedMemorySize, SMEM_BYTES);
    cudaFuncSetAttribute(gemm2_kernel, cudaFuncAttributeMaxDynamicSharedMemorySize, SMEM_BYTES);

    prep_kernel<<<2048, 256>>>(hs, wgu, dn, sel);
    gemm1_kernel<<<dim3(MAX_TILES, I_ / 64), THREADS, SMEM_BYTES>>>();
    gemm2_kernel<<<dim3(MAX_TILES, H_ / 128), THREADS, SMEM_BYTES>>>(out);
}